// round 11
// baseline (speedup 1.0000x reference)
#include <cuda_runtime.h>
#include <cuda_fp16.h>
#include <cstdint>

#define DD 128
#define SMAX 4096
#define NMAX 1048576

// ---------------- scratch (device globals; no allocs allowed) ----------------
__device__ float   g_xs[SMAX * DD];            // segment sums (fp32)
__device__ float   g_xm[SMAX * DD];            // xs @ Lambda^T (fp32)
__device__ __half  g_xh[(size_t)NMAX * DD];    // fp16 copy of x (256 MB)
__device__ __half  g_Gh[DD * DD];              // fp16 Gamma_W

__device__ __forceinline__ uint32_t smem_u32(const void* p) {
    uint32_t a;
    asm("{ .reg .u64 t; cvta.to.shared.u64 t, %1; cvt.u32.u64 %0, t; }"
        : "=r"(a) : "l"(p));
    return a;
}
__device__ __forceinline__ void cp_async16(uint32_t dst, const void* src) {
    asm volatile("cp.async.cg.shared.global [%0], [%1], 16;"
                 :: "r"(dst), "l"(src));
}
// 16B-unit swizzle: row-dependent XOR keeps ldmatrix 8-row reads conflict-free
#define SWZB(u, lr3) ((((((u) ^ (lr3)) & 7) | ((u) & 8))) << 4)

// ---------------- kernel 0: zero xs + convert Gamma_W -> fp16 ----------------
__global__ void prep_kernel(const float* __restrict__ GW) {
    int i = blockIdx.x * blockDim.x + threadIdx.x;
    if (i < SMAX * DD) g_xs[i] = 0.0f;
    if (i < DD * DD)   g_Gh[i] = __float2half(GW[i]);
}

// ---------------- kernel 1: segment sum + fp16 convert, ping-pong batches ---
#define SS_ROWS 128
__global__ __launch_bounds__(256) void segsum_kernel(
    const float* __restrict__ x, const int* __restrict__ seg, int n)
{
    int lane = threadIdx.x & 31;
    int w = blockIdx.x * 8 + (threadIdx.x >> 5);
    int base = w * SS_ROWS;
    if (base >= n) return;
    int limit = n - base; if (limit > SS_ROWS) limit = SS_ROWS;

    float4 acc = make_float4(0.f, 0.f, 0.f, 0.f);
    int cur = -1;

    int nb = limit >> 3;          // full 8-row batches
    int ss[2][8]; float4 vv[2][8];
    if (nb > 0) {
        #pragma unroll
        for (int j = 0; j < 8; j++) ss[0][j] = seg[base + j];
        #pragma unroll
        for (int j = 0; j < 8; j++)
            vv[0][j] = __ldcs((const float4*)(x + (size_t)(base + j) * DD + lane * 4));
    }
    for (int b = 0; b < nb; b++) {
        int pb = b & 1;
        if (b + 1 < nb) {
            int row = base + (b + 1) * 8;
            #pragma unroll
            for (int j = 0; j < 8; j++) ss[pb ^ 1][j] = seg[row + j];
            #pragma unroll
            for (int j = 0; j < 8; j++)
                vv[pb ^ 1][j] = __ldcs((const float4*)(x + (size_t)(row + j) * DD + lane * 4));
        }
        int row = base + b * 8;
        #pragma unroll
        for (int j = 0; j < 8; j++) {
            float4 v = vv[pb][j]; int s = ss[pb][j];
            if (s != cur) {
                if (cur >= 0) {
                    float* p = g_xs + (size_t)cur * DD + lane * 4;
                    atomicAdd(p + 0, acc.x); atomicAdd(p + 1, acc.y);
                    atomicAdd(p + 2, acc.z); atomicAdd(p + 3, acc.w);
                }
                acc = make_float4(0.f, 0.f, 0.f, 0.f);
                cur = s;
            }
            acc.x += v.x; acc.y += v.y; acc.z += v.z; acc.w += v.w;
            __half2 h0 = __float22half2_rn(make_float2(v.x, v.y));
            __half2 h1 = __float22half2_rn(make_float2(v.z, v.w));
            uint2 pk = make_uint2(reinterpret_cast<uint32_t&>(h0),
                                  reinterpret_cast<uint32_t&>(h1));
            __stcs((uint2*)(g_xh + (size_t)(row + j) * DD + lane * 4), pk);
        }
    }
    for (int r = nb * 8; r < limit; r++) {
        int row = base + r;
        int s = seg[row];
        float4 v = __ldcs((const float4*)(x + (size_t)row * DD + lane * 4));
        if (s != cur) {
            if (cur >= 0) {
                float* p = g_xs + (size_t)cur * DD + lane * 4;
                atomicAdd(p + 0, acc.x); atomicAdd(p + 1, acc.y);
                atomicAdd(p + 2, acc.z); atomicAdd(p + 3, acc.w);
            }
            acc = make_float4(0.f, 0.f, 0.f, 0.f);
            cur = s;
        }
        acc.x += v.x; acc.y += v.y; acc.z += v.z; acc.w += v.w;
        __half2 h0 = __float22half2_rn(make_float2(v.x, v.y));
        __half2 h1 = __float22half2_rn(make_float2(v.z, v.w));
        uint2 pk = make_uint2(reinterpret_cast<uint32_t&>(h0),
                              reinterpret_cast<uint32_t&>(h1));
        __stcs((uint2*)(g_xh + (size_t)row * DD + lane * 4), pk);
    }
    if (cur >= 0) {
        float* p = g_xs + (size_t)cur * DD + lane * 4;
        atomicAdd(p + 0, acc.x); atomicAdd(p + 1, acc.y);
        atomicAdd(p + 2, acc.z); atomicAdd(p + 3, acc.w);
    }
}

// ---------------- kernel 2: xm = xs @ Lambda^T (fp32, 16 segs/block) --------
__global__ __launch_bounds__(128) void xm_kernel(const float* __restrict__ LW) {
    __shared__ float xsh[16 * DD];
    int t = threadIdx.x;
    int s0 = blockIdx.x * 16;
    #pragma unroll
    for (int j = 0; j < 16; j++)
        xsh[j * DD + t] = g_xs[(size_t)(s0 + j) * DD + t];
    __syncthreads();
    float acc[16];
    #pragma unroll
    for (int j = 0; j < 16; j++) acc[j] = 0.0f;
    const float* lrow = LW + (size_t)t * DD;
    #pragma unroll 4
    for (int k = 0; k < DD; k++) {
        float lw = lrow[k];
        #pragma unroll
        for (int j = 0; j < 16; j++) acc[j] += xsh[j * DD + k] * lw;
    }
    #pragma unroll
    for (int j = 0; j < 16; j++)
        g_xm[(size_t)(s0 + j) * DD + t] = acc[j];
}

// ---- kernel 3: persistent HMMA GEMM, f16 accumulators, hoisted xm loads ----
// CTA tile 128x128; 8 warps as 4(M) x 2(N), warp tile 32x64.
// smem: As[0] 32KB | As[1] 32KB | Bs 32KB | bias = 96.5 KB (2 CTAs/SM)
#define A_BYTES 32768
#define BIAS_SOFF (3 * A_BYTES)
#define GEMM_SMEM (BIAS_SOFF + 1024)

__device__ __forceinline__ void stage_A128(uint32_t dstbase, int t, int n, int tid) {
    int m0 = t * 128;
    #pragma unroll
    for (int i = 0; i < 8; i++) {
        int idx = tid + i * 256, row = idx >> 4, u = idx & 15;
        int gr = m0 + row; if (gr >= n) gr = n - 1;   // clamp; garbage never stored
        cp_async16(dstbase + row * 256 + SWZB(u, row & 7),
                   g_xh + (size_t)gr * DD + u * 8);
    }
}

__global__ __launch_bounds__(256, 2) void gemm_kernel(
    const int* __restrict__ seg, const float* __restrict__ bias,
    float* __restrict__ out, int n, int ntiles)
{
    extern __shared__ char smraw[];
    uint32_t sb = smem_u32(smraw);
    uint32_t As[2] = { sb, sb + A_BYTES };
    uint32_t Bs = sb + 2 * A_BYTES;
    float* bsm = (float*)(smraw + BIAS_SOFF);

    int tid = threadIdx.x, lane = tid & 31, wid = tid >> 5;

    // bias -> smem; stage B (Gamma fp16) once + first A tile, one group
    if (tid < DD) bsm[tid] = bias[tid];
    #pragma unroll
    for (int i = 0; i < 8; i++) {
        int idx = tid + i * 256, row = idx >> 4, u = idx & 15;
        cp_async16(Bs + row * 256 + SWZB(u, row & 7), g_Gh + row * DD + u * 8);
    }
    stage_A128(As[0], blockIdx.x, n, tid);
    asm volatile("cp.async.commit_group;");

    // lane geometry: warps 4(M) x 2(N); warp tile 32 x 64
    int wm = (wid & 3) * 32, wn = (wid >> 2) * 64;
    int g = lane >> 3, lr = lane & 7;
    int qr = lane >> 2, qc = 2 * (lane & 3);
    int a_m = (g & 1) * 8 + lr;
    int b_n = (g >> 1) * 8 + lr;
    int ua0 = g >> 1, ub0 = g & 1;

    uint32_t a_off[2], b_base[4];
    #pragma unroll
    for (int tm = 0; tm < 2; tm++) a_off[tm] = (uint32_t)((wm + a_m + tm * 16) * 256);
    #pragma unroll
    for (int p = 0; p < 4; p++) b_base[p] = Bs + (uint32_t)((wn + b_n + p * 16) * 256);

    int buf = 0;
    for (int t = blockIdx.x; t < ntiles; t += gridDim.x, buf ^= 1) {
        asm volatile("cp.async.wait_group 0;" ::: "memory");
        __syncthreads();

        int tnext = t + gridDim.x;
        if (tnext < ntiles) {
            stage_A128(As[buf ^ 1], tnext, n, tid);
            asm volatile("cp.async.commit_group;");
        }

        int m0 = t * 128;
        bool full = (m0 + 128 <= n);
        int sid[2][2];
        #pragma unroll
        for (int tm = 0; tm < 2; tm++)
            #pragma unroll
            for (int half = 0; half < 2; half++) {
                int m = m0 + wm + tm * 16 + qr + half * 8;
                sid[tm][half] = (full || m < n) ? seg[m] : 0;
            }

        // hoist tm=0 xm loads above the mma loop: latency hidden by tensor work
        float2 xv0[2][8];
        #pragma unroll
        for (int half = 0; half < 2; half++) {
            const float* __restrict__ xmr = g_xm + (size_t)sid[0][half] * DD;
            #pragma unroll
            for (int tn = 0; tn < 8; tn++)
                xv0[half][tn] = *(const float2*)(xmr + wn + tn * 8 + qc);
        }

        uint32_t acc[2][8][2];   // f16x2 accumulators
        #pragma unroll
        for (int a = 0; a < 2; a++)
            #pragma unroll
            for (int b = 0; b < 8; b++) { acc[a][b][0] = 0u; acc[a][b][1] = 0u; }

        uint32_t ab = As[buf];
        #pragma unroll
        for (int kk = 0; kk < 8; kk++) {
            uint32_t asw = (uint32_t)SWZB(ua0 + 2 * kk, lr);
            uint32_t bsw = (uint32_t)SWZB(ub0 + 2 * kk, lr);
            uint32_t afrag[2][4];
            #pragma unroll
            for (int tm = 0; tm < 2; tm++) {
                asm volatile("ldmatrix.sync.aligned.m8n8.x4.shared.b16 "
                             "{%0,%1,%2,%3}, [%4];"
                             : "=r"(afrag[tm][0]), "=r"(afrag[tm][1]),
                               "=r"(afrag[tm][2]), "=r"(afrag[tm][3])
                             : "r"(ab + a_off[tm] + asw));
            }
            uint32_t bfrag[4][4];
            #pragma unroll
            for (int p = 0; p < 4; p++) {
                asm volatile("ldmatrix.sync.aligned.m8n8.x4.shared.b16 "
                             "{%0,%1,%2,%3}, [%4];"
                             : "=r"(bfrag[p][0]), "=r"(bfrag[p][1]),
                               "=r"(bfrag[p][2]), "=r"(bfrag[p][3])
                             : "r"(b_base[p] + bsw));
            }
            #pragma unroll
            for (int tm = 0; tm < 2; tm++) {
                #pragma unroll
                for (int tn = 0; tn < 8; tn++) {
                    uint32_t br0 = bfrag[tn >> 1][(tn & 1) * 2];
                    uint32_t br1 = bfrag[tn >> 1][(tn & 1) * 2 + 1];
                    asm volatile(
                        "mma.sync.aligned.m16n8k16.row.col.f16.f16.f16.f16 "
                        "{%0,%1}, {%2,%3,%4,%5}, {%6,%7}, {%0,%1};"
                        : "+r"(acc[tm][tn][0]), "+r"(acc[tm][tn][1])
                        : "r"(afrag[tm][0]), "r"(afrag[tm][1]),
                          "r"(afrag[tm][2]), "r"(afrag[tm][3]),
                          "r"(br0), "r"(br1));
                }
            }
        }

        // epilogue: tm=0 uses hoisted xv0; tm=1 batches loads before stores
        #pragma unroll
        for (int half = 0; half < 2; half++) {
            int m = m0 + wm + qr + half * 8;
            if (!full && m >= n) continue;
            float* __restrict__ orow = out + (size_t)m * DD;
            #pragma unroll
            for (int tn = 0; tn < 8; tn++) {
                int nc = wn + tn * 8 + qc;
                float2 bv = *(const float2*)(bsm + nc);
                float2 dv = __half22float2(
                    *reinterpret_cast<__half2*>(&acc[0][tn][half]));
                float2 rr;
                rr.x = dv.x + bv.x - xv0[half][tn].x;
                rr.y = dv.y + bv.y - xv0[half][tn].y;
                *(float2*)(orow + nc) = rr;
            }
        }
        #pragma unroll
        for (int half = 0; half < 2; half++) {
            int m = m0 + wm + 16 + qr + half * 8;
            if (!full && m >= n) continue;
            const float* __restrict__ xmr = g_xm + (size_t)sid[1][half] * DD;
            float2 xv[8];
            #pragma unroll
            for (int tn = 0; tn < 8; tn++)
                xv[tn] = *(const float2*)(xmr + wn + tn * 8 + qc);
            float* __restrict__ orow = out + (size_t)m * DD;
            #pragma unroll
            for (int tn = 0; tn < 8; tn++) {
                int nc = wn + tn * 8 + qc;
                float2 bv = *(const float2*)(bsm + nc);
                float2 dv = __half22float2(
                    *reinterpret_cast<__half2*>(&acc[1][tn][half]));
                float2 rr;
                rr.x = dv.x + bv.x - xv[tn].x;
                rr.y = dv.y + bv.y - xv[tn].y;
                *(float2*)(orow + nc) = rr;
            }
        }
    }
}

// ---------------- launch ----------------
extern "C" void kernel_launch(void* const* d_in, const int* in_sizes, int n_in,
                              void* d_out, int out_size)
{
    const float* x   = (const float*)d_in[0];
    const int*   seg = (const int*)d_in[1];
    // d_in[2] = num_segments (statically 4096 here)
    const float* GW  = (const float*)d_in[3];
    const float* Gb  = (const float*)d_in[4];
    const float* LW  = (const float*)d_in[5];
    float* out = (float*)d_out;
    int n = in_sizes[0] / DD;
    int ntiles = (n + 127) / 128;

    cudaFuncSetAttribute(gemm_kernel,
                         cudaFuncAttributeMaxDynamicSharedMemorySize, GEMM_SMEM);

    prep_kernel<<<(SMAX * DD + 255) / 256, 256>>>(GW);
    int nwarps = (n + SS_ROWS - 1) / SS_ROWS;
    segsum_kernel<<<(nwarps + 7) / 8, 256>>>(x, seg, n);
    xm_kernel<<<SMAX / 16, 128>>>(LW);
    int grid = 296; if (grid > ntiles) grid = ntiles;
    gemm_kernel<<<grid, 256, GEMM_SMEM>>>(seg, Gb, out, n, ntiles);
}

// round 13
// speedup vs baseline: 1.3725x; 1.3725x over previous
#include <cuda_runtime.h>
#include <cuda_fp16.h>
#include <cstdint>

#define DD 128
#define SMAX 4096
#define NMAX 1048576

// ---------------- scratch (device globals; no allocs allowed) ----------------
__device__ float   g_xs[SMAX * DD];            // segment sums (fp32)
__device__ float   g_xm[SMAX * DD];            // xs @ Lambda^T (fp32)
__device__ __half  g_xh[(size_t)NMAX * DD];    // fp16 copy of x (256 MB)

__device__ __forceinline__ uint32_t smem_u32(const void* p) {
    uint32_t a;
    asm("{ .reg .u64 t; cvta.to.shared.u64 t, %1; cvt.u32.u64 %0, t; }"
        : "=r"(a) : "l"(p));
    return a;
}
__device__ __forceinline__ void cp_async16(uint32_t dst, const void* src) {
    asm volatile("cp.async.cg.shared.global [%0], [%1], 16;"
                 :: "r"(dst), "l"(src));
}
// 16B-unit swizzle: row-dependent XOR keeps ldmatrix 8-row reads conflict-free
#define SWZB(u, lr3) ((((((u) ^ (lr3)) & 7) | ((u) & 8))) << 4)

// ---------------- kernel 0: zero xs ----------------
__global__ void zero_xs_kernel() {
    int i = blockIdx.x * blockDim.x + threadIdx.x;
    ((float4*)g_xs)[i] = make_float4(0.f, 0.f, 0.f, 0.f);
}

// ---------------- kernel 1: segment sum + fp16 convert (R10 body) ----------
#define SS_ROWS 128
__global__ __launch_bounds__(256) void segsum_kernel(
    const float* __restrict__ x, const int* __restrict__ seg, int n)
{
    int lane = threadIdx.x & 31;
    int w = blockIdx.x * 8 + (threadIdx.x >> 5);
    int base = w * SS_ROWS;
    if (base >= n) return;
    int limit = n - base; if (limit > SS_ROWS) limit = SS_ROWS;

    float4 acc = make_float4(0.f, 0.f, 0.f, 0.f);
    int cur = -1;

    int r = 0;
    for (; r + 8 <= limit; r += 8) {
        int row = base + r;
        int ss[8]; float4 vv[8];
        #pragma unroll
        for (int j = 0; j < 8; j++) ss[j] = seg[row + j];
        #pragma unroll
        for (int j = 0; j < 8; j++)
            vv[j] = __ldcs((const float4*)(x + (size_t)(row + j) * DD + lane * 4));
        #pragma unroll
        for (int j = 0; j < 8; j++) {
            float4 v = vv[j]; int s = ss[j];
            if (s != cur) {
                if (cur >= 0) {
                    float* p = g_xs + (size_t)cur * DD + lane * 4;
                    atomicAdd(p + 0, acc.x); atomicAdd(p + 1, acc.y);
                    atomicAdd(p + 2, acc.z); atomicAdd(p + 3, acc.w);
                }
                acc = make_float4(0.f, 0.f, 0.f, 0.f);
                cur = s;
            }
            acc.x += v.x; acc.y += v.y; acc.z += v.z; acc.w += v.w;
            __half2 h0 = __float22half2_rn(make_float2(v.x, v.y));
            __half2 h1 = __float22half2_rn(make_float2(v.z, v.w));
            uint2 pk = make_uint2(reinterpret_cast<uint32_t&>(h0),
                                  reinterpret_cast<uint32_t&>(h1));
            __stcs((uint2*)(g_xh + (size_t)(row + j) * DD + lane * 4), pk);
        }
    }
    for (; r < limit; r++) {
        int row = base + r;
        int s = seg[row];
        float4 v = __ldcs((const float4*)(x + (size_t)row * DD + lane * 4));
        if (s != cur) {
            if (cur >= 0) {
                float* p = g_xs + (size_t)cur * DD + lane * 4;
                atomicAdd(p + 0, acc.x); atomicAdd(p + 1, acc.y);
                atomicAdd(p + 2, acc.z); atomicAdd(p + 3, acc.w);
            }
            acc = make_float4(0.f, 0.f, 0.f, 0.f);
            cur = s;
        }
        acc.x += v.x; acc.y += v.y; acc.z += v.z; acc.w += v.w;
        __half2 h0 = __float22half2_rn(make_float2(v.x, v.y));
        __half2 h1 = __float22half2_rn(make_float2(v.z, v.w));
        uint2 pk = make_uint2(reinterpret_cast<uint32_t&>(h0),
                              reinterpret_cast<uint32_t&>(h1));
        __stcs((uint2*)(g_xh + (size_t)row * DD + lane * 4), pk);
    }
    if (cur >= 0) {
        float* p = g_xs + (size_t)cur * DD + lane * 4;
        atomicAdd(p + 0, acc.x); atomicAdd(p + 1, acc.y);
        atomicAdd(p + 2, acc.z); atomicAdd(p + 3, acc.w);
    }
}

// ------- kernel 2: xm = xs @ Lambda^T; LW staged in smem, pitch 129 --------
__global__ __launch_bounds__(128) void xm_kernel(const float* __restrict__ LW) {
    extern __shared__ float lsh[];          // 128 x pitch-129
    __shared__ float xsh[16 * DD];
    int t = threadIdx.x;
    for (int i = t; i < DD * DD; i += 128) {
        int rr = i >> 7, cc = i & 127;
        lsh[rr * 129 + cc] = LW[i];          // coalesced read, conflict-free write
    }
    int s0 = blockIdx.x * 16;
    #pragma unroll
    for (int j = 0; j < 16; j++)
        xsh[j * DD + t] = g_xs[(size_t)(s0 + j) * DD + t];
    __syncthreads();
    float acc[16];
    #pragma unroll
    for (int j = 0; j < 16; j++) acc[j] = 0.0f;
    const float* lrow = lsh + t * 129;       // stride 129 -> all banks distinct
    #pragma unroll 4
    for (int k = 0; k < DD; k++) {
        float lw = lrow[k];
        #pragma unroll
        for (int j = 0; j < 16; j++) acc[j] += xsh[j * DD + k] * lw;
    }
    #pragma unroll
    for (int j = 0; j < 16; j++)
        g_xm[(size_t)(s0 + j) * DD + t] = acc[j];
}

// ---- kernel 3: persistent HMMA GEMM (R10 structure), fp16 in / f32 acc ----
// CTA tile 128x128; 8 warps as 4(M) x 2(N), warp tile 32x64.
// smem: As[0] 32KB | As[1] 32KB | Bs 32KB | bias = 96.5 KB (2 CTAs/SM)
#define A_BYTES 32768
#define BIAS_SOFF (3 * A_BYTES)
#define GEMM_SMEM (BIAS_SOFF + 1024)

__device__ __forceinline__ void stage_A128(uint32_t dstbase, int t, int n, int tid) {
    int m0 = t * 128;
    #pragma unroll
    for (int i = 0; i < 8; i++) {
        int idx = tid + i * 256, row = idx >> 4, u = idx & 15;
        int gr = m0 + row; if (gr >= n) gr = n - 1;   // clamp; garbage never stored
        cp_async16(dstbase + row * 256 + SWZB(u, row & 7),
                   g_xh + (size_t)gr * DD + u * 8);
    }
}

__global__ __launch_bounds__(256, 2) void gemm_kernel(
    const int* __restrict__ seg, const float* __restrict__ GW,
    const float* __restrict__ bias, float* __restrict__ out, int n, int ntiles)
{
    extern __shared__ char smraw[];
    uint32_t sb = smem_u32(smraw);
    uint32_t As[2] = { sb, sb + A_BYTES };
    uint32_t Bs = sb + 2 * A_BYTES;
    float* bsm = (float*)(smraw + BIAS_SOFF);
    char* smp = smraw;

    int tid = threadIdx.x, lane = tid & 31, wid = tid >> 5;

    // first A tile via cp.async
    stage_A128(As[0], blockIdx.x, n, tid);
    asm volatile("cp.async.commit_group;");

    // bias -> smem; Gamma fp32 -> fp16 swizzled smem (L2-cached, once per CTA)
    if (tid < DD) bsm[tid] = bias[tid];
    #pragma unroll
    for (int i = 0; i < 8; i++) {
        int idx = tid + i * 256, row = idx >> 4, u = idx & 15;
        const float* gsrc = GW + row * DD + u * 8;
        float4 f0 = *(const float4*)(gsrc);
        float4 f1 = *(const float4*)(gsrc + 4);
        __half2 h0 = __float22half2_rn(make_float2(f0.x, f0.y));
        __half2 h1 = __float22half2_rn(make_float2(f0.z, f0.w));
        __half2 h2 = __float22half2_rn(make_float2(f1.x, f1.y));
        __half2 h3 = __float22half2_rn(make_float2(f1.z, f1.w));
        uint4 pk = make_uint4(reinterpret_cast<uint32_t&>(h0),
                              reinterpret_cast<uint32_t&>(h1),
                              reinterpret_cast<uint32_t&>(h2),
                              reinterpret_cast<uint32_t&>(h3));
        *(uint4*)(smp + 2 * A_BYTES + row * 256 + SWZB(u, row & 7)) = pk;
    }

    // lane geometry: warps 4(M) x 2(N); warp tile 32 x 64
    int wm = (wid & 3) * 32, wn = (wid >> 2) * 64;
    int g = lane >> 3, lr = lane & 7;
    int qr = lane >> 2, qc = 2 * (lane & 3);
    int a_m = (g & 1) * 8 + lr;
    int b_n = (g >> 1) * 8 + lr;
    int ua0 = g >> 1, ub0 = g & 1;

    uint32_t a_off[2], b_base[4];
    #pragma unroll
    for (int tm = 0; tm < 2; tm++) a_off[tm] = (uint32_t)((wm + a_m + tm * 16) * 256);
    #pragma unroll
    for (int p = 0; p < 4; p++) b_base[p] = Bs + (uint32_t)((wn + b_n + p * 16) * 256);

    int buf = 0;
    for (int t = blockIdx.x; t < ntiles; t += gridDim.x, buf ^= 1) {
        asm volatile("cp.async.wait_group 0;" ::: "memory");
        __syncthreads();

        int tnext = t + gridDim.x;
        if (tnext < ntiles) {
            stage_A128(As[buf ^ 1], tnext, n, tid);
            asm volatile("cp.async.commit_group;");
        }

        int m0 = t * 128;
        bool full = (m0 + 128 <= n);
        int sid[2][2];
        #pragma unroll
        for (int tm = 0; tm < 2; tm++)
            #pragma unroll
            for (int half = 0; half < 2; half++) {
                int m = m0 + wm + tm * 16 + qr + half * 8;
                sid[tm][half] = (full || m < n) ? seg[m] : 0;
            }

        float acc[2][8][4];
        #pragma unroll
        for (int a = 0; a < 2; a++)
            #pragma unroll
            for (int b = 0; b < 8; b++)
                #pragma unroll
                for (int c = 0; c < 4; c++) acc[a][b][c] = 0.0f;

        uint32_t ab = As[buf];
        #pragma unroll
        for (int kk = 0; kk < 8; kk++) {
            uint32_t asw = (uint32_t)SWZB(ua0 + 2 * kk, lr);
            uint32_t bsw = (uint32_t)SWZB(ub0 + 2 * kk, lr);
            uint32_t afrag[2][4];
            #pragma unroll
            for (int tm = 0; tm < 2; tm++) {
                asm volatile("ldmatrix.sync.aligned.m8n8.x4.shared.b16 "
                             "{%0,%1,%2,%3}, [%4];"
                             : "=r"(afrag[tm][0]), "=r"(afrag[tm][1]),
                               "=r"(afrag[tm][2]), "=r"(afrag[tm][3])
                             : "r"(ab + a_off[tm] + asw));
            }
            uint32_t bfrag[4][4];
            #pragma unroll
            for (int p = 0; p < 4; p++) {
                asm volatile("ldmatrix.sync.aligned.m8n8.x4.shared.b16 "
                             "{%0,%1,%2,%3}, [%4];"
                             : "=r"(bfrag[p][0]), "=r"(bfrag[p][1]),
                               "=r"(bfrag[p][2]), "=r"(bfrag[p][3])
                             : "r"(b_base[p] + bsw));
            }
            #pragma unroll
            for (int tm = 0; tm < 2; tm++) {
                #pragma unroll
                for (int tn = 0; tn < 8; tn++) {
                    uint32_t br0 = bfrag[tn >> 1][(tn & 1) * 2];
                    uint32_t br1 = bfrag[tn >> 1][(tn & 1) * 2 + 1];
                    asm volatile(
                        "mma.sync.aligned.m16n8k16.row.col.f32.f16.f16.f32 "
                        "{%0,%1,%2,%3}, {%4,%5,%6,%7}, {%8,%9}, {%0,%1,%2,%3};"
                        : "+f"(acc[tm][tn][0]), "+f"(acc[tm][tn][1]),
                          "+f"(acc[tm][tn][2]), "+f"(acc[tm][tn][3])
                        : "r"(afrag[tm][0]), "r"(afrag[tm][1]),
                          "r"(afrag[tm][2]), "r"(afrag[tm][3]),
                          "r"(br0), "r"(br1));
                }
            }
        }

        // epilogue: batch ALL xm loads of a group into regs BEFORE any store
        #pragma unroll
        for (int tm = 0; tm < 2; tm++) {
            #pragma unroll
            for (int half = 0; half < 2; half++) {
                int m = m0 + wm + tm * 16 + qr + half * 8;
                if (!full && m >= n) continue;
                const float* __restrict__ xmr = g_xm + (size_t)sid[tm][half] * DD;
                float2 xv[8];
                #pragma unroll
                for (int tn = 0; tn < 8; tn++)
                    xv[tn] = *(const float2*)(xmr + wn + tn * 8 + qc);
                float* __restrict__ orow = out + (size_t)m * DD;
                #pragma unroll
                for (int tn = 0; tn < 8; tn++) {
                    int nc = wn + tn * 8 + qc;
                    float2 bv = *(const float2*)(bsm + nc);
                    float2 rr;
                    rr.x = acc[tm][tn][half * 2 + 0] + bv.x - xv[tn].x;
                    rr.y = acc[tm][tn][half * 2 + 1] + bv.y - xv[tn].y;
                    *(float2*)(orow + nc) = rr;
                }
            }
        }
    }
}

// ---------------- launch ----------------
extern "C" void kernel_launch(void* const* d_in, const int* in_sizes, int n_in,
                              void* d_out, int out_size)
{
    const float* x   = (const float*)d_in[0];
    const int*   seg = (const int*)d_in[1];
    // d_in[2] = num_segments (statically 4096 here)
    const float* GW  = (const float*)d_in[3];
    const float* Gb  = (const float*)d_in[4];
    const float* LW  = (const float*)d_in[5];
    float* out = (float*)d_out;
    int n = in_sizes[0] / DD;
    int ntiles = (n + 127) / 128;

    cudaFuncSetAttribute(gemm_kernel,
                         cudaFuncAttributeMaxDynamicSharedMemorySize, GEMM_SMEM);
    cudaFuncSetAttribute(xm_kernel,
                         cudaFuncAttributeMaxDynamicSharedMemorySize, 128 * 129 * 4);

    zero_xs_kernel<<<SMAX * DD / 4 / 256, 256>>>();
    int nwarps = (n + SS_ROWS - 1) / SS_ROWS;
    segsum_kernel<<<(nwarps + 7) / 8, 256>>>(x, seg, n);
    xm_kernel<<<SMAX / 16, 128, 128 * 129 * 4>>>(LW);
    int grid = 296; if (grid > ntiles) grid = ntiles;
    gemm_kernel<<<grid, 256, GEMM_SMEM>>>(seg, GW, Gb, out, n, ntiles);
}